// round 16
// baseline (speedup 1.0000x reference)
#include <cuda_runtime.h>
#include <cuda_fp16.h>

#define EN 131072
#define NN 4096
#define BB 4
#define CC 128
#define OO 127
#define CAP 96   // bucket capacity (max observed degree ~55; 11-sigma slack)

// ---------------- scratch (device globals; no allocation) ----------------
__device__ __half g_xTh[(size_t)BB * NN * CC];  // fp16 x^T [b][n][c] (4 MB)
__device__ __half g_WTh[256 * 136];             // W fp16 [k][o] padded rows
__device__ __align__(16) int g_cnt[NN];  // ticket ctr == cnt(idx_i) after bucket
__device__ __align__(16) int g_deg[NN];  // deg(idx_j)
__device__ int g_dst[NN * CAP];          // bucketed neighbor lists

// ---------------- small kernels ----------------
__global__ void k_zero() {
    int t = blockIdx.x * blockDim.x + threadIdx.x;  // 8192 threads
    if (t < NN) g_cnt[t] = 0;
    else g_deg[t - NN] = 0;
}

// single-pass edge classification: hist + scatter + deg in one kernel
__global__ void k_bucket(const int* __restrict__ ii, const int* __restrict__ jj) {
    int e = blockIdx.x * blockDim.x + threadIdx.x;
    int i = ii[e];
    int j = jj[e];
    int t = atomicAdd(&g_cnt[i], 1);
    g_dst[i * CAP + t] = j;
    atomicAdd(&g_deg[j], 1);
}

// transpose x[b][c][n] -> fp16 xTh[b][n][c]  +  build fp16 W [k][136]
__global__ void k_prep(const float* __restrict__ x, const float* __restrict__ W) {
    if (blockIdx.x < 2048) {
        __shared__ float tile[32][33];
        const int bt = blockIdx.x;
        const int b = bt >> 9;
        const int c0 = ((bt >> 7) & 3) * 32;
        const int n0 = (bt & 127) * 32;
        const int tx = threadIdx.x & 31, ty = threadIdx.x >> 5;
#pragma unroll
        for (int r = 0; r < 4; r++)
            tile[ty + 8 * r][tx] =
                x[((size_t)(b * CC + c0 + ty + 8 * r)) * NN + n0 + tx];
        __syncthreads();
        __half2* dst = reinterpret_cast<__half2*>(g_xTh);
#pragma unroll
        for (int i = 0; i < 2; i++) {
            int id = threadIdx.x + 256 * i;
            int c2 = id & 15, nl = id >> 4;
            __half2 h = __floats2half2_rn(tile[2 * c2][nl], tile[2 * c2 + 1][nl]);
            dst[((size_t)(b * NN + n0 + nl)) * 64 + (c0 >> 1) + c2] = h;
        }
    } else {
        int bw = blockIdx.x - 2048;  // 16 blocks
#pragma unroll
        for (int i = 0; i < 8; i++) {
            int idx = bw * 256 + threadIdx.x + 4096 * i;  // [0, 32768)
            int o = idx & 127, k = idx >> 7;
            float v = 0.0f;
            if (o < OO) v = W[(o * CC + (k & 127)) * 2 + (k >> 7)];
            g_WTh[k * 136 + o] = __float2half_rn(v);
        }
    }
}

// ---------------- fused gather + HMMA GEMM ----------------
__device__ __forceinline__ void accum8(float* a, uint4 v) {
    float2 t0 = __half22float2(*reinterpret_cast<const __half2*>(&v.x));
    float2 t1 = __half22float2(*reinterpret_cast<const __half2*>(&v.y));
    float2 t2 = __half22float2(*reinterpret_cast<const __half2*>(&v.z));
    float2 t3 = __half22float2(*reinterpret_cast<const __half2*>(&v.w));
    a[0] += t0.x; a[1] += t0.y; a[2] += t1.x; a[3] += t1.y;
    a[4] += t2.x; a[5] += t2.y; a[6] += t3.x; a[7] += t3.y;
}

// gather neighbor sums -> fp16 S_s [128 rows][136 halfs].
// cp.async software pipeline: per-warp 3-buffer staging ring (2KB/buf);
// edge order (and thus fp32 rounding) identical to the register version.
__device__ __forceinline__ void do_gather(int b, int n0, int tid, __half* S_s,
                                          unsigned stgSh) {
    const int w = tid >> 5;
    const int l = tid & 31;
    const int lh = l >> 4;
    const int lc = l & 15;
    const uint4* xb =
        reinterpret_cast<const uint4*>(g_xTh) + (size_t)b * NN * 16;
    const unsigned myStg = stgSh + w * 6144 + lc * 16;

    int m = w;
    int nn = n0 + m;
    int cnt = g_cnt[nn];
    int iA = g_dst[nn * CAP + l];
    int iB = g_dst[nn * CAP + 32 + l];
#pragma unroll 1
    for (int mi = 0; mi < 8; mi++) {
        int cnt_n = 0, iA_n = 0, iB_n = 0;
        if (mi < 7) {
            cnt_n = g_cnt[nn + 16];
            iA_n = g_dst[(nn + 16) * CAP + l];
            iB_n = g_dst[(nn + 16) * CAP + 32 + l];
        }
        float a[8] = {0.f, 0.f, 0.f, 0.f, 0.f, 0.f, 0.f, 0.f};
        const int c64 = cnt < 64 ? cnt : 64;
        const int ngrp = c64 >> 3;

        auto issue_grp = [&](int gq, int buf) {
            const unsigned dbase = myStg + buf * 2048;
#pragma unroll
            for (int k = 0; k < 4; k++) {
                const int ee = gq * 8 + lh + 2 * k;
                const int j = (gq < 4)
                                  ? __shfl_sync(0xffffffffu, iA, ee)
                                  : __shfl_sync(0xffffffffu, iB, ee - 32);
                const void* src = reinterpret_cast<const char*>(
                                      xb + (size_t)j * 16) + lc * 16;
                const unsigned d = dbase + (unsigned)((lh + 2 * k) * 256);
                asm volatile("cp.async.ca.shared.global [%0], [%1], 16;\n"
                             :: "r"(d), "l"(src));
            }
            asm volatile("cp.async.commit_group;\n" ::: "memory");
        };

        if (ngrp > 0) issue_grp(0, 0);
        if (ngrp > 1) issue_grp(1, 1);
#pragma unroll 1
        for (int gq = 0; gq < ngrp; gq++) {
            if (gq + 2 < ngrp) issue_grp(gq + 2, (gq + 2) % 3);
            const int rem = ngrp - 1 - gq;
            if (rem >= 2)
                asm volatile("cp.async.wait_group 2;" ::: "memory");
            else if (rem == 1)
                asm volatile("cp.async.wait_group 1;" ::: "memory");
            else
                asm volatile("cp.async.wait_group 0;" ::: "memory");
            __syncwarp();
            const unsigned rbase = myStg + (gq % 3) * 2048;
#pragma unroll
            for (int k = 0; k < 4; k++) {
                uint4 v;
                asm volatile("ld.shared.v4.u32 {%0,%1,%2,%3}, [%4];"
                             : "=r"(v.x), "=r"(v.y), "=r"(v.z), "=r"(v.w)
                             : "r"(rbase + (unsigned)((lh + 2 * k) * 256)));
                accum8(a, v);
            }
        }

        // remainder edges [ngrp*8, c64) via register path (same edge order)
        int p = ngrp * 8;
        for (; p < c64; p += 2) {
            const int ee = p + lh;
            const int jA = __shfl_sync(0xffffffffu, iA, ee & 31);
            const int jB = __shfl_sync(0xffffffffu, iB, ee & 31);
            const int j = (ee < 32) ? jA : jB;
            if (lh == 0 || c64 - p > 1) {
                uint4 v = __ldcg(xb + (size_t)j * 16 + lc);
                accum8(a, v);
            }
        }
        for (p = 64; p < cnt; p += 2) {  // rare tail, exactness fallback
            if (lh == 0 || cnt - p > 1) {
                int j = g_dst[nn * CAP + p + lh];
                uint4 v = __ldcg(xb + (size_t)j * 16 + lc);
                accum8(a, v);
            }
        }
#pragma unroll
        for (int q = 0; q < 8; q++)
            a[q] += __shfl_down_sync(0xffffffffu, a[q], 16);
        if (lh == 0) {
            __half2 hh[4];
            hh[0] = __floats2half2_rn(a[0], a[1]);
            hh[1] = __floats2half2_rn(a[2], a[3]);
            hh[2] = __floats2half2_rn(a[4], a[5]);
            hh[3] = __floats2half2_rn(a[6], a[7]);
            *reinterpret_cast<uint4*>(&S_s[m * 136 + lc * 8]) =
                *reinterpret_cast<const uint4*>(hh);
        }
        m += 16; nn += 16;
        cnt = cnt_n; iA = iA_n; iB = iB_n;
    }
}

__device__ __forceinline__ void ldmA(unsigned* a, unsigned addr) {
    asm volatile(
        "ldmatrix.sync.aligned.m8n8.x4.shared.b16 {%0,%1,%2,%3}, [%4];"
        : "=r"(a[0]), "=r"(a[1]), "=r"(a[2]), "=r"(a[3]) : "r"(addr));
}
__device__ __forceinline__ void ldmBT(unsigned* b, unsigned addr) {
    asm volatile(
        "ldmatrix.sync.aligned.m8n8.x4.trans.shared.b16 {%0,%1,%2,%3}, [%4];"
        : "=r"(b[0]), "=r"(b[1]), "=r"(b[2]), "=r"(b[3]) : "r"(addr));
}
__device__ __forceinline__ void mma16816(float* d, const unsigned* a,
                                         const unsigned* b) {
    asm volatile(
        "mma.sync.aligned.m16n8k16.row.col.f32.f16.f16.f32 "
        "{%0,%1,%2,%3},{%4,%5,%6,%7},{%8,%9},{%0,%1,%2,%3};"
        : "+f"(d[0]), "+f"(d[1]), "+f"(d[2]), "+f"(d[3])
        : "r"(a[0]), "r"(a[1]), "r"(a[2]), "r"(a[3]), "r"(b[0]), "r"(b[1]));
}

// one K=128 pass: warp tile 16n x 64o; A rows padded 272 B; W rows 272 B.
template <bool INIT>
__device__ __forceinline__ void gemm_pass(float acc[8][4], unsigned aBase,
                                          unsigned bBase) {
    if (INIT) {
#pragma unroll
        for (int t = 0; t < 8; t++)
#pragma unroll
            for (int i = 0; i < 4; i++) acc[t][i] = 0.f;
    }
#pragma unroll
    for (int ks = 0; ks < 8; ks++) {
        unsigned a[4];
        ldmA(a, aBase + ks * 32);
#pragma unroll
        for (int q = 0; q < 4; q++) {
            unsigned bb[4];
            ldmBT(bb, bBase + ks * 4352 + q * 32);
            mma16816(acc[2 * q + 0], a, bb + 0);
            mma16816(acc[2 * q + 1], a, bb + 2);
        }
    }
}

// smem: W 69632 | AS (A then S, shared) 34816 | bias 512 | stage 98304
#define SMEM_AS   69632
#define SMEM_BIAS 104448
#define SMEM_STG  104960
#define SMEMB     203264

__global__ void __launch_bounds__(512, 1)
k_fused(const float* __restrict__ bias, float* __restrict__ out) {
    extern __shared__ __align__(16) unsigned char smraw[];
    __half* W_s = reinterpret_cast<__half*>(smraw);
    __half* AS_s = reinterpret_cast<__half*>(smraw + SMEM_AS);
    float* bias_s = reinterpret_cast<float*>(smraw + SMEM_BIAS);

    const int b   = blockIdx.y;
    const int n0  = blockIdx.x * 128;
    const int tid = threadIdx.x;

    const int lane = tid & 31;
    const int w = tid >> 5;          // 16 warps
    const int mw = w & 7;            // n tile: rows 16*mw
    const int ow = (w >> 3) * 64;    // o range
    const int g = lane >> 3, r = lane & 7;

    const unsigned aOff = (unsigned)((mw * 16 + (g & 1) * 8 + r) * 272 +
                                     (g >> 1) * 16);
    const unsigned bOff = (unsigned)(((g & 1) * 8 + r) * 272 + (g >> 1) * 16 +
                                     ow * 2);
    const unsigned Wsh = (unsigned)__cvta_generic_to_shared(W_s);
    const unsigned ASsh = (unsigned)__cvta_generic_to_shared(AS_s);
    const unsigned StgSh =
        (unsigned)__cvta_generic_to_shared(smraw + SMEM_STG);

    // per-thread output rows + cnt factors (for the mid-kernel transform)
    const int nr0 = n0 + mw * 16 + (lane >> 2);
    const int nr1 = nr0 + 8;
    const float cf0 = (float)g_cnt[nr0];
    const float cf1 = (float)g_cnt[nr1];

    float acc[8][4];

    // ---- stage W, A (= xTh rows, fp16), bias ----
    {
        const uint4* gw = reinterpret_cast<const uint4*>(g_WTh);
        uint4* ws4 = reinterpret_cast<uint4*>(W_s);
#pragma unroll
        for (int i = 0; i < 8; i++) ws4[tid + 512 * i] = gw[tid + 512 * i];
        if (tid < 256) ws4[tid + 4096] = gw[tid + 4096];
        const uint4* gx = reinterpret_cast<const uint4*>(g_xTh) +
                          ((size_t)b * NN + n0) * 16;
#pragma unroll
        for (int i = 0; i < 4; i++) {
            int id = tid + 512 * i;  // 0..2047
            int n = id >> 4, q = id & 15;
            *reinterpret_cast<uint4*>(&AS_s[n * 136 + q * 8]) = gx[n * 16 + q];
        }
        if (tid < OO) bias_s[tid] = bias[tid];
        if (tid == OO) bias_s[OO] = 0.0f;
    }
    __syncthreads();

    // ---- pass 1: acc = x~ * W0 ----
    gemm_pass<true>(acc, ASsh + aOff, Wsh + bOff);

    // fold in place: acc <- cf * (acc + bias)
#pragma unroll
    for (int t = 0; t < 8; t++) {
        const int o0 = ow + t * 8 + (lane & 3) * 2;
        const float b0 = bias_s[o0];
        const float b1 = bias_s[o0 + 1];
        acc[t][0] = cf0 * (acc[t][0] + b0);
        acc[t][1] = cf0 * (acc[t][1] + b1);
        acc[t][2] = cf1 * (acc[t][2] + b0);
        acc[t][3] = cf1 * (acc[t][3] + b1);
    }
    __syncthreads();  // all warps done reading AS_s as A

    // ---- gather S into AS_s (cp.async pipeline) ----
    do_gather(b, n0, tid, AS_s, StgSh);
    __syncthreads();

    // ---- pass 2: acc += S * W1 ----
    gemm_pass<false>(acc, ASsh + aOff, Wsh + bOff + 34816u);

    // ---- epilogue: y = acc / max(deg,1); o=127 lane -> deg ----
    const int d0 = g_deg[nr0], d1 = g_deg[nr1];
    const float dg0 = (float)d0, dg1 = (float)d1;
    const float inv0 = 1.0f / (float)(d0 > 0 ? d0 : 1);
    const float inv1 = 1.0f / (float)(d1 > 0 ? d1 : 1);
    const size_t ob = (size_t)b * 128;
#pragma unroll
    for (int t = 0; t < 8; t++) {
        const int o0 = ow + t * 8 + (lane & 3) * 2;
        const int o1 = o0 + 1;
        float y00 = acc[t][0] * inv0;
        float y01 = acc[t][1] * inv0;
        float y10 = acc[t][2] * inv1;
        float y11 = acc[t][3] * inv1;
        if (o1 == OO) { y01 = dg0; y11 = dg1; }
        out[(ob + o0) * NN + nr0] = y00;
        out[(ob + o1) * NN + nr0] = y01;
        out[(ob + o0) * NN + nr1] = y10;
        out[(ob + o1) * NN + nr1] = y11;
    }
}

// ---------------- launch (fork/join multi-stream capture) ----------------
extern "C" void kernel_launch(void* const* d_in, const int* in_sizes, int n_in,
                              void* d_out, int out_size) {
    const float* x = nullptr;
    const float* W = nullptr;
    const float* bias = nullptr;
    const int* ii = nullptr;
    const int* jj = nullptr;
    for (int i = 0; i < n_in; i++) {
        int s = in_sizes[i];
        if (s == BB * CC * NN) x = (const float*)d_in[i];
        else if (s == OO * CC * 2) W = (const float*)d_in[i];
        else if (s == OO) bias = (const float*)d_in[i];
        else if (s == EN) {
            if (!ii) ii = (const int*)d_in[i];
            else jj = (const int*)d_in[i];
        }
    }
    float* out = (float*)d_out;

    static cudaStream_t s2 = nullptr;
    static cudaEvent_t evFork = nullptr, evJ2 = nullptr;
    if (!s2) {
        cudaStreamCreateWithFlags(&s2, cudaStreamNonBlocking);
        cudaEventCreateWithFlags(&evFork, cudaEventDisableTiming);
        cudaEventCreateWithFlags(&evJ2, cudaEventDisableTiming);
        cudaFuncSetAttribute(k_fused,
                             cudaFuncAttributeMaxDynamicSharedMemorySize,
                             SMEMB);
    }

    cudaEventRecord(evFork, 0);
    cudaStreamWaitEvent(s2, evFork, 0);

    // s2: transpose + weight repack
    k_prep<<<2064, 256, 0, s2>>>(x, W);
    cudaEventRecord(evJ2, s2);

    // main: zero counters -> single-pass bucket scatter (hist+csr+deg merged)
    k_zero<<<16, 512>>>();
    k_bucket<<<EN / 256, 256>>>(ii, jj);

    // join, then fused gather + HMMA GEMM (single wave: 128 blocks)
    cudaStreamWaitEvent(0, evJ2, 0);
    k_fused<<<dim3(NN / 128, BB), 512, SMEMB>>>(bias, out);
}

// round 17
// speedup vs baseline: 1.1110x; 1.1110x over previous
#include <cuda_runtime.h>
#include <cuda_fp16.h>

#define EN 131072
#define NN 4096
#define BB 4
#define CC 128
#define OO 127
#define CAP 96   // bucket capacity (max observed degree ~55; 11-sigma slack)

// ---------------- scratch (device globals; no allocation) ----------------
__device__ __half g_xTh[(size_t)BB * NN * CC];  // fp16 x^T [b][n][c] (4 MB)
__device__ __half g_WTh[256 * 136];             // W fp16 [k][o] padded rows
__device__ __align__(16) int g_cnt[NN];  // ticket ctr == cnt(idx_i) after bucket
__device__ __align__(16) int g_deg[NN];  // deg(idx_j)
__device__ int g_dst[NN * CAP];          // bucketed neighbor lists

// ---------------- small kernels ----------------
__global__ void k_zero() {
    int t = blockIdx.x * blockDim.x + threadIdx.x;  // 8192 threads
    if (t < NN) g_cnt[t] = 0;
    else g_deg[t - NN] = 0;
}

// single-pass edge classification: hist + scatter + deg in one kernel
__global__ void k_bucket(const int* __restrict__ ii, const int* __restrict__ jj) {
    int e = blockIdx.x * blockDim.x + threadIdx.x;
    int i = ii[e];
    int j = jj[e];
    int t = atomicAdd(&g_cnt[i], 1);
    g_dst[i * CAP + t] = j;
    atomicAdd(&g_deg[j], 1);
}

// transpose x[b][c][n] -> fp16 xTh[b][n][c]  +  build fp16 W [k][136]
__global__ void k_prep(const float* __restrict__ x, const float* __restrict__ W) {
    if (blockIdx.x < 2048) {
        __shared__ float tile[32][33];
        const int bt = blockIdx.x;
        const int b = bt >> 9;
        const int c0 = ((bt >> 7) & 3) * 32;
        const int n0 = (bt & 127) * 32;
        const int tx = threadIdx.x & 31, ty = threadIdx.x >> 5;
#pragma unroll
        for (int r = 0; r < 4; r++)
            tile[ty + 8 * r][tx] =
                x[((size_t)(b * CC + c0 + ty + 8 * r)) * NN + n0 + tx];
        __syncthreads();
        __half2* dst = reinterpret_cast<__half2*>(g_xTh);
#pragma unroll
        for (int i = 0; i < 2; i++) {
            int id = threadIdx.x + 256 * i;
            int c2 = id & 15, nl = id >> 4;
            __half2 h = __floats2half2_rn(tile[2 * c2][nl], tile[2 * c2 + 1][nl]);
            dst[((size_t)(b * NN + n0 + nl)) * 64 + (c0 >> 1) + c2] = h;
        }
    } else {
        int bw = blockIdx.x - 2048;  // 16 blocks
#pragma unroll
        for (int i = 0; i < 8; i++) {
            int idx = bw * 256 + threadIdx.x + 4096 * i;  // [0, 32768)
            int o = idx & 127, k = idx >> 7;
            float v = 0.0f;
            if (o < OO) v = W[(o * CC + (k & 127)) * 2 + (k >> 7)];
            g_WTh[k * 136 + o] = __float2half_rn(v);
        }
    }
}

// ---------------- fused gather + HMMA GEMM ----------------
__device__ __forceinline__ void accum8(float* a, uint4 v) {
    float2 t0 = __half22float2(*reinterpret_cast<const __half2*>(&v.x));
    float2 t1 = __half22float2(*reinterpret_cast<const __half2*>(&v.y));
    float2 t2 = __half22float2(*reinterpret_cast<const __half2*>(&v.z));
    float2 t3 = __half22float2(*reinterpret_cast<const __half2*>(&v.w));
    a[0] += t0.x; a[1] += t0.y; a[2] += t1.x; a[3] += t1.y;
    a[4] += t2.x; a[5] += t2.y; a[6] += t3.x; a[7] += t3.y;
}

// pair two fp16 edge rows with HADD2, then one fp32 accumulate (37% fewer
// instructions in the gather consume stream; one extra fp16 rounding)
__device__ __forceinline__ void accumPair(float* a, uint4 u, uint4 v) {
    uint4 s;
    *reinterpret_cast<__half2*>(&s.x) =
        __hadd2(*reinterpret_cast<const __half2*>(&u.x),
                *reinterpret_cast<const __half2*>(&v.x));
    *reinterpret_cast<__half2*>(&s.y) =
        __hadd2(*reinterpret_cast<const __half2*>(&u.y),
                *reinterpret_cast<const __half2*>(&v.y));
    *reinterpret_cast<__half2*>(&s.z) =
        __hadd2(*reinterpret_cast<const __half2*>(&u.z),
                *reinterpret_cast<const __half2*>(&v.z));
    *reinterpret_cast<__half2*>(&s.w) =
        __hadd2(*reinterpret_cast<const __half2*>(&u.w),
                *reinterpret_cast<const __half2*>(&v.w));
    accum8(a, s);
}

// gather neighbor sums -> fp16 S_s [128 rows][136 halfs].
// 16 warps, rows stride 16; register-resident indices + shuffle distribution.
// 16-edge groups put 8 independent LDG.128 in flight per thread (MLP=8).
__device__ __forceinline__ void do_gather(int b, int n0, int tid, __half* S_s) {
    const int w = tid >> 5;
    const int l = tid & 31;
    const int lh = l >> 4;
    const int lc = l & 15;
    const uint4* xb =
        reinterpret_cast<const uint4*>(g_xTh) + (size_t)b * NN * 16;
    int m = w;
    int nn = n0 + m;
    int cnt = g_cnt[nn];
    int iA = g_dst[nn * CAP + l];
    int iB = g_dst[nn * CAP + 32 + l];
#pragma unroll 1
    for (int mi = 0; mi < 8; mi++) {
        int cnt_n = 0, iA_n = 0, iB_n = 0;
        if (mi < 7) {
            cnt_n = g_cnt[nn + 16];
            iA_n = g_dst[(nn + 16) * CAP + l];
            iB_n = g_dst[(nn + 16) * CAP + 32 + l];
        }
        float a[8] = {0.f, 0.f, 0.f, 0.f, 0.f, 0.f, 0.f, 0.f};
        const int c1 = cnt < 32 ? cnt : 32;
        int p = 0;
        for (; p + 16 <= c1; p += 16) {
            int j0 = __shfl_sync(0xffffffffu, iA, p + 0 + lh);
            int j1 = __shfl_sync(0xffffffffu, iA, p + 2 + lh);
            int j2 = __shfl_sync(0xffffffffu, iA, p + 4 + lh);
            int j3 = __shfl_sync(0xffffffffu, iA, p + 6 + lh);
            int j4 = __shfl_sync(0xffffffffu, iA, p + 8 + lh);
            int j5 = __shfl_sync(0xffffffffu, iA, p + 10 + lh);
            int j6 = __shfl_sync(0xffffffffu, iA, p + 12 + lh);
            int j7 = __shfl_sync(0xffffffffu, iA, p + 14 + lh);
            uint4 v0 = __ldcg(xb + (size_t)j0 * 16 + lc);
            uint4 v1 = __ldcg(xb + (size_t)j1 * 16 + lc);
            uint4 v2 = __ldcg(xb + (size_t)j2 * 16 + lc);
            uint4 v3 = __ldcg(xb + (size_t)j3 * 16 + lc);
            uint4 v4 = __ldcg(xb + (size_t)j4 * 16 + lc);
            uint4 v5 = __ldcg(xb + (size_t)j5 * 16 + lc);
            uint4 v6 = __ldcg(xb + (size_t)j6 * 16 + lc);
            uint4 v7 = __ldcg(xb + (size_t)j7 * 16 + lc);
            accumPair(a, v0, v1); accumPair(a, v2, v3);
            accumPair(a, v4, v5); accumPair(a, v6, v7);
        }
        for (; p + 8 <= c1; p += 8) {
            int j0 = __shfl_sync(0xffffffffu, iA, p + 0 + lh);
            int j1 = __shfl_sync(0xffffffffu, iA, p + 2 + lh);
            int j2 = __shfl_sync(0xffffffffu, iA, p + 4 + lh);
            int j3 = __shfl_sync(0xffffffffu, iA, p + 6 + lh);
            uint4 v0 = __ldcg(xb + (size_t)j0 * 16 + lc);
            uint4 v1 = __ldcg(xb + (size_t)j1 * 16 + lc);
            uint4 v2 = __ldcg(xb + (size_t)j2 * 16 + lc);
            uint4 v3 = __ldcg(xb + (size_t)j3 * 16 + lc);
            accumPair(a, v0, v1); accumPair(a, v2, v3);
        }
        for (; p < c1; p += 2) {
            int j = __shfl_sync(0xffffffffu, iA, p + lh);
            if (lh == 0 || c1 - p > 1) {
                uint4 v = __ldcg(xb + (size_t)j * 16 + lc);
                accum8(a, v);
            }
        }
        if (cnt > 32) {
            const int c2 = cnt < 64 ? cnt : 64;
            p = 32;
            for (; p + 16 <= c2; p += 16) {
                int q = p - 32 + lh;
                int j0 = __shfl_sync(0xffffffffu, iB, q + 0);
                int j1 = __shfl_sync(0xffffffffu, iB, q + 2);
                int j2 = __shfl_sync(0xffffffffu, iB, q + 4);
                int j3 = __shfl_sync(0xffffffffu, iB, q + 6);
                int j4 = __shfl_sync(0xffffffffu, iB, q + 8);
                int j5 = __shfl_sync(0xffffffffu, iB, q + 10);
                int j6 = __shfl_sync(0xffffffffu, iB, q + 12);
                int j7 = __shfl_sync(0xffffffffu, iB, q + 14);
                uint4 v0 = __ldcg(xb + (size_t)j0 * 16 + lc);
                uint4 v1 = __ldcg(xb + (size_t)j1 * 16 + lc);
                uint4 v2 = __ldcg(xb + (size_t)j2 * 16 + lc);
                uint4 v3 = __ldcg(xb + (size_t)j3 * 16 + lc);
                uint4 v4 = __ldcg(xb + (size_t)j4 * 16 + lc);
                uint4 v5 = __ldcg(xb + (size_t)j5 * 16 + lc);
                uint4 v6 = __ldcg(xb + (size_t)j6 * 16 + lc);
                uint4 v7 = __ldcg(xb + (size_t)j7 * 16 + lc);
                accumPair(a, v0, v1); accumPair(a, v2, v3);
                accumPair(a, v4, v5); accumPair(a, v6, v7);
            }
            for (; p + 8 <= c2; p += 8) {
                int q = p - 32 + lh;
                int j0 = __shfl_sync(0xffffffffu, iB, q + 0);
                int j1 = __shfl_sync(0xffffffffu, iB, q + 2);
                int j2 = __shfl_sync(0xffffffffu, iB, q + 4);
                int j3 = __shfl_sync(0xffffffffu, iB, q + 6);
                uint4 v0 = __ldcg(xb + (size_t)j0 * 16 + lc);
                uint4 v1 = __ldcg(xb + (size_t)j1 * 16 + lc);
                uint4 v2 = __ldcg(xb + (size_t)j2 * 16 + lc);
                uint4 v3 = __ldcg(xb + (size_t)j3 * 16 + lc);
                accumPair(a, v0, v1); accumPair(a, v2, v3);
            }
            for (; p < c2; p += 2) {
                int j = __shfl_sync(0xffffffffu, iB, p - 32 + lh);
                if (lh == 0 || c2 - p > 1) {
                    uint4 v = __ldcg(xb + (size_t)j * 16 + lc);
                    accum8(a, v);
                }
            }
            for (p = 64; p < cnt; p += 2) {  // rare tail, exactness fallback
                if (lh == 0 || cnt - p > 1) {
                    int j = g_dst[nn * CAP + p + lh];
                    uint4 v = __ldcg(xb + (size_t)j * 16 + lc);
                    accum8(a, v);
                }
            }
        }
#pragma unroll
        for (int q = 0; q < 8; q++)
            a[q] += __shfl_down_sync(0xffffffffu, a[q], 16);
        if (lh == 0) {
            __half2 hh[4];
            hh[0] = __floats2half2_rn(a[0], a[1]);
            hh[1] = __floats2half2_rn(a[2], a[3]);
            hh[2] = __floats2half2_rn(a[4], a[5]);
            hh[3] = __floats2half2_rn(a[6], a[7]);
            *reinterpret_cast<uint4*>(&S_s[m * 136 + lc * 8]) =
                *reinterpret_cast<const uint4*>(hh);
        }
        m += 16; nn += 16;
        cnt = cnt_n; iA = iA_n; iB = iB_n;
    }
}

__device__ __forceinline__ void ldmA(unsigned* a, unsigned addr) {
    asm volatile(
        "ldmatrix.sync.aligned.m8n8.x4.shared.b16 {%0,%1,%2,%3}, [%4];"
        : "=r"(a[0]), "=r"(a[1]), "=r"(a[2]), "=r"(a[3]) : "r"(addr));
}
__device__ __forceinline__ void ldmBT(unsigned* b, unsigned addr) {
    asm volatile(
        "ldmatrix.sync.aligned.m8n8.x4.trans.shared.b16 {%0,%1,%2,%3}, [%4];"
        : "=r"(b[0]), "=r"(b[1]), "=r"(b[2]), "=r"(b[3]) : "r"(addr));
}
__device__ __forceinline__ void mma16816(float* d, const unsigned* a,
                                         const unsigned* b) {
    asm volatile(
        "mma.sync.aligned.m16n8k16.row.col.f32.f16.f16.f32 "
        "{%0,%1,%2,%3},{%4,%5,%6,%7},{%8,%9},{%0,%1,%2,%3};"
        : "+f"(d[0]), "+f"(d[1]), "+f"(d[2]), "+f"(d[3])
        : "r"(a[0]), "r"(a[1]), "r"(a[2]), "r"(a[3]), "r"(b[0]), "r"(b[1]));
}

// one K=128 pass: warp tile 16n x 64o; A rows padded 272 B; W rows 272 B.
// INIT=true zeroes acc at entry so acc isn't live before the call.
template <bool INIT>
__device__ __forceinline__ void gemm_pass(float acc[8][4], unsigned aBase,
                                          unsigned bBase) {
    if (INIT) {
#pragma unroll
        for (int t = 0; t < 8; t++)
#pragma unroll
            for (int i = 0; i < 4; i++) acc[t][i] = 0.f;
    }
#pragma unroll
    for (int ks = 0; ks < 8; ks++) {
        unsigned a[4];
        ldmA(a, aBase + ks * 32);
#pragma unroll
        for (int q = 0; q < 4; q++) {
            unsigned bb[4];
            ldmBT(bb, bBase + ks * 4352 + q * 32);
            mma16816(acc[2 * q + 0], a, bb + 0);
            mma16816(acc[2 * q + 1], a, bb + 2);
        }
    }
}

// smem: W 256*136h (69632) | A 128*136h (34816) | S 128*136h (34816) | bias 512
#define SMEMB 139776

__global__ void __launch_bounds__(512, 1)
k_fused(const float* __restrict__ bias, float* __restrict__ out) {
    extern __shared__ __align__(16) unsigned char smraw[];
    __half* W_s = reinterpret_cast<__half*>(smraw);
    __half* A_s = W_s + 256 * 136;
    __half* S_s = A_s + 128 * 136;
    float* bias_s = reinterpret_cast<float*>(S_s + 128 * 136);

    const int b   = blockIdx.y;
    const int n0  = blockIdx.x * 128;
    const int tid = threadIdx.x;
    const bool gemmFirst = (blockIdx.x & 1);

    const int lane = tid & 31;
    const int w = tid >> 5;          // 16 warps
    const int mw = w & 7;            // n tile: rows 16*mw
    const int ow = (w >> 3) * 64;    // o range
    const int g = lane >> 3, r = lane & 7;

    const unsigned aOff = (unsigned)((mw * 16 + (g & 1) * 8 + r) * 272 +
                                     (g >> 1) * 16);
    const unsigned bOff = (unsigned)(((g & 1) * 8 + r) * 272 + (g >> 1) * 16 +
                                     ow * 2);
    const unsigned Wsh = (unsigned)__cvta_generic_to_shared(W_s);
    const unsigned Ash = (unsigned)__cvta_generic_to_shared(A_s);
    const unsigned Ssh = (unsigned)__cvta_generic_to_shared(S_s);

    // per-thread output rows + cnt factors (for the mid-kernel transform)
    const int nr0 = n0 + mw * 16 + (lane >> 2);
    const int nr1 = nr0 + 8;
    const float cf0 = (float)g_cnt[nr0];
    const float cf1 = (float)g_cnt[nr1];

    float acc[8][4];

    auto do_copies = [&]() {
        const uint4* gw = reinterpret_cast<const uint4*>(g_WTh);
        uint4* ws4 = reinterpret_cast<uint4*>(W_s);
#pragma unroll
        for (int i = 0; i < 8; i++) ws4[tid + 512 * i] = gw[tid + 512 * i];
        if (tid < 256) ws4[tid + 4096] = gw[tid + 4096];
        const uint4* gx = reinterpret_cast<const uint4*>(g_xTh) +
                          ((size_t)b * NN + n0) * 16;
#pragma unroll
        for (int i = 0; i < 4; i++) {
            int id = tid + 512 * i;  // 0..2047
            int n = id >> 4, q = id & 15;
            *reinterpret_cast<uint4*>(&A_s[n * 136 + q * 8]) = gx[n * 16 + q];
        }
        if (tid < OO) bias_s[tid] = bias[tid];
        if (tid == OO) bias_s[OO] = 0.0f;
    };

    // fold pass-1 result in place: acc <- cf * (acc + bias)
    auto transform = [&]() {
#pragma unroll
        for (int t = 0; t < 8; t++) {
            const int o0 = ow + t * 8 + (lane & 3) * 2;
            const float b0 = bias_s[o0];
            const float b1 = bias_s[o0 + 1];
            acc[t][0] = cf0 * (acc[t][0] + b0);
            acc[t][1] = cf0 * (acc[t][1] + b1);
            acc[t][2] = cf1 * (acc[t][2] + b0);
            acc[t][3] = cf1 * (acc[t][3] + b1);
        }
    };

    if (gemmFirst) {
        do_copies();
        __syncthreads();
        gemm_pass<true>(acc, Ash + aOff, Wsh + bOff);
        transform();
        do_gather(b, n0, tid, S_s);
        __syncthreads();
        gemm_pass<false>(acc, Ssh + aOff, Wsh + bOff + 34816u);
    } else {
        do_gather(b, n0, tid, S_s);  // acc not yet live: regs free for MLP
        do_copies();
        __syncthreads();
        gemm_pass<true>(acc, Ash + aOff, Wsh + bOff);
        transform();
        gemm_pass<false>(acc, Ssh + aOff, Wsh + bOff + 34816u);
    }

    // ---- epilogue: y = acc / max(deg,1); o=127 lane -> deg ----
    const int d0 = g_deg[nr0], d1 = g_deg[nr1];
    const float dg0 = (float)d0, dg1 = (float)d1;
    const float inv0 = 1.0f / (float)(d0 > 0 ? d0 : 1);
    const float inv1 = 1.0f / (float)(d1 > 0 ? d1 : 1);
    const size_t ob = (size_t)b * 128;
#pragma unroll
    for (int t = 0; t < 8; t++) {
        const int o0 = ow + t * 8 + (lane & 3) * 2;
        const int o1 = o0 + 1;
        float y00 = acc[t][0] * inv0;
        float y01 = acc[t][1] * inv0;
        float y10 = acc[t][2] * inv1;
        float y11 = acc[t][3] * inv1;
        if (o1 == OO) { y01 = dg0; y11 = dg1; }
        out[(ob + o0) * NN + nr0] = y00;
        out[(ob + o1) * NN + nr0] = y01;
        out[(ob + o0) * NN + nr1] = y10;
        out[(ob + o1) * NN + nr1] = y11;
    }
}

// ---------------- launch (fork/join multi-stream capture) ----------------
extern "C" void kernel_launch(void* const* d_in, const int* in_sizes, int n_in,
                              void* d_out, int out_size) {
    const float* x = nullptr;
    const float* W = nullptr;
    const float* bias = nullptr;
    const int* ii = nullptr;
    const int* jj = nullptr;
    for (int i = 0; i < n_in; i++) {
        int s = in_sizes[i];
        if (s == BB * CC * NN) x = (const float*)d_in[i];
        else if (s == OO * CC * 2) W = (const float*)d_in[i];
        else if (s == OO) bias = (const float*)d_in[i];
        else if (s == EN) {
            if (!ii) ii = (const int*)d_in[i];
            else jj = (const int*)d_in[i];
        }
    }
    float* out = (float*)d_out;

    static cudaStream_t s2 = nullptr;
    static cudaEvent_t evFork = nullptr, evJ2 = nullptr;
    if (!s2) {
        cudaStreamCreateWithFlags(&s2, cudaStreamNonBlocking);
        cudaEventCreateWithFlags(&evFork, cudaEventDisableTiming);
        cudaEventCreateWithFlags(&evJ2, cudaEventDisableTiming);
        cudaFuncSetAttribute(k_fused,
                             cudaFuncAttributeMaxDynamicSharedMemorySize,
                             SMEMB);
    }

    cudaEventRecord(evFork, 0);
    cudaStreamWaitEvent(s2, evFork, 0);

    // s2: transpose + weight repack
    k_prep<<<2064, 256, 0, s2>>>(x, W);
    cudaEventRecord(evJ2, s2);

    // main: zero counters -> single-pass bucket scatter (hist+csr+deg merged)
    k_zero<<<16, 512>>>();
    k_bucket<<<EN / 256, 256>>>(ii, jj);

    // join, then fused gather + HMMA GEMM (single wave: 128 blocks)
    cudaStreamWaitEvent(0, evJ2, 0);
    k_fused<<<dim3(NN / 128, BB), 512, SMEMB>>>(bias, out);
}